// round 16
// baseline (speedup 1.0000x reference)
#include <cuda_runtime.h>
#include <cstdint>

// ctrl_pts: (16,64,64,4) f32 | uspan/vspan: (512,) i32 | Nu/Nv: (512,4) f32
// out: (16,512,512,3) f32
#define BATCH   16
#define MCTRL   64
#define NCTRL   64
#define OUTN    512
#define PDEG    3

typedef unsigned long long ull;

__device__ __forceinline__ ull pack2(float a, float b) {
    ull r; asm("mov.b64 %0, {%1,%2};" : "=l"(r) : "f"(a), "f"(b)); return r;
}
__device__ __forceinline__ void unpack2(ull v, float& a, float& b) {
    asm("mov.b64 {%0,%1}, %2;" : "=f"(a), "=f"(b) : "l"(v));
}
__device__ __forceinline__ ull mul2(ull a, ull b) {
    ull d; asm("mul.rn.f32x2 %0, %1, %2;" : "=l"(d) : "l"(a), "l"(b)); return d;
}
__device__ __forceinline__ ull fma2(ull a, ull b, ull c) {
    ull d; asm("fma.rn.f32x2 %0, %1, %2, %3;" : "=l"(d) : "l"(a), "l"(b), "l"(c)); return d;
}
__device__ __forceinline__ float rcp_approx(float x) {
    float r; asm("rcp.approx.f32 %0, %1;" : "=f"(r) : "f"(x)); return r;
}
__device__ __forceinline__ uint32_t smem_u32(const void* p) {
    uint32_t a;
    asm("{ .reg .u64 t; cvta.to.shared.u64 t, %1; cvt.u32.u64 %0, t; }"
        : "=r"(a) : "l"(p));
    return a;
}

// ---------------------------------------------------------------------------
// Fused kernel. Block = (b, 4 u-rows), 256 threads, 6 blocks/SM (75% occ).
// Phase 1: A[4][64] into smem — one entry per thread.
// Phase 2: thread g owns v-pair (2g, 2g+1); 9 packed weights.
// Drain:   pipelined TMA bulk stores (2 x 12KB); only the second drain's
//          latency is exposed at block tail.
// ---------------------------------------------------------------------------
__global__ __launch_bounds__(256, 6)
void surf_fused(const float4* __restrict__ ctrl,
                const int*    __restrict__ uspan,
                const int2*   __restrict__ vspan2,
                const float4* __restrict__ Nu4,
                const float4* __restrict__ Nv4,
                char*         __restrict__ out)
{
    __shared__ float4 sA[4 * NCTRL];                     // 4 KB
    __shared__ __align__(16) ull sOut[4 * 768];          // 24 KB = 2 x 12 KB halves

    int t  = threadIdx.x;                     // 0..255
    int b  = blockIdx.y;
    int u0 = blockIdx.x * 4;

    // ---- phase-2 weight setup (hoisted: overlaps phase-1 LDGs) ----
    int g = t;
    int2 vs  = __ldg(vspan2 + g);
    int  iv0 = vs.x - PDEG;
    bool sh  = vs.y != vs.x;

    ull wp0[4], wp1[5];
    {
        float4 nv0 = __ldg(Nv4 + 2 * g);
        float4 nv1 = __ldg(Nv4 + 2 * g + 1);
        wp0[0] = pack2(nv0.x, nv0.x);
        wp0[1] = pack2(nv0.y, nv0.y);
        wp0[2] = pack2(nv0.z, nv0.z);
        wp0[3] = pack2(nv0.w, nv0.w);
        float w0 = sh ? 0.0f : nv1.x;
        float w1 = sh ? nv1.x : nv1.y;
        float w2 = sh ? nv1.y : nv1.z;
        float w3 = sh ? nv1.z : nv1.w;
        float w4 = sh ? nv1.w : 0.0f;
        wp1[0] = pack2(w0, w0);
        wp1[1] = pack2(w1, w1);
        wp1[2] = pack2(w2, w2);
        wp1[3] = pack2(w3, w3);
        wp1[4] = pack2(w4, w4);
    }

    // ---------------- Phase 1: one A entry per thread ----------------
    {
        int n  = t & (NCTRL - 1);
        int ul = t >> 6;                      // 0..3
        int u  = u0 + ul;
        int iu0 = __ldg(uspan + u) - PDEG;
        const float4* __restrict__ base =
            ctrl + ((b * MCTRL + iu0) * NCTRL + n);
        float4 c0 = __ldg(base + 0 * NCTRL);
        float4 c1 = __ldg(base + 1 * NCTRL);
        float4 c2 = __ldg(base + 2 * NCTRL);
        float4 c3 = __ldg(base + 3 * NCTRL);
        float4 nu = __ldg(Nu4 + u);

        float4 acc;
        acc.x = nu.x*c0.x + nu.y*c1.x + nu.z*c2.x + nu.w*c3.x;
        acc.y = nu.x*c0.y + nu.y*c1.y + nu.z*c2.y + nu.w*c3.y;
        acc.z = nu.x*c0.z + nu.y*c1.z + nu.z*c2.z + nu.w*c3.z;
        acc.w = nu.x*c0.w + nu.y*c1.w + nu.z*c2.w + nu.w*c3.w;

        sA[ul * NCTRL + n] = acc;
    }
    __syncthreads();

    // ---------------- Phase 2: two halves of 2 rows each ----------------
#pragma unroll
    for (int hp = 0; hp < 2; hp++) {
#pragma unroll
        for (int ir = 0; ir < 2; ir++) {
            int i = 2 * hp + ir;
            const ulonglong2* __restrict__ Ab =
                (const ulonglong2*)(sA + i * NCTRL + iv0);
            ulonglong2 A0 = Ab[0];
            ulonglong2 A1 = Ab[1];
            ulonglong2 A2 = Ab[2];
            ulonglong2 A3 = Ab[3];
            ulonglong2 A4 = Ab[4];

            // v0: 4 taps (window never shifted for first v of the pair)
            ull xy0 = mul2(wp0[0], A0.x);
            ull zw0 = mul2(wp0[0], A0.y);
            xy0 = fma2(wp0[1], A1.x, xy0);  zw0 = fma2(wp0[1], A1.y, zw0);
            xy0 = fma2(wp0[2], A2.x, xy0);  zw0 = fma2(wp0[2], A2.y, zw0);
            xy0 = fma2(wp0[3], A3.x, xy0);  zw0 = fma2(wp0[3], A3.y, zw0);

            // v1: 5 taps
            ull xy1 = mul2(wp1[0], A0.x);
            ull zw1 = mul2(wp1[0], A0.y);
            xy1 = fma2(wp1[1], A1.x, xy1);  zw1 = fma2(wp1[1], A1.y, zw1);
            xy1 = fma2(wp1[2], A2.x, xy1);  zw1 = fma2(wp1[2], A2.y, zw1);
            xy1 = fma2(wp1[3], A3.x, xy1);  zw1 = fma2(wp1[3], A3.y, zw1);
            xy1 = fma2(wp1[4], A4.x, xy1);  zw1 = fma2(wp1[4], A4.y, zw1);

            // Packed epilogue -> 24B per thread, gmem-layout order.
            float sz0, sw0, sz1, sw1;
            unpack2(zw0, sz0, sw0);
            unpack2(zw1, sz1, sw1);
            float inv0 = rcp_approx(sw0);
            float inv1 = rcp_approx(sw1);

            ull c0 = mul2(xy0, pack2(inv0, inv0));     // (x0', y0')
            ull xy1s = mul2(xy1, pack2(inv1, inv1));
            float x1s, y1s;
            unpack2(xy1s, x1s, y1s);
            ull c1 = pack2(sz0 * inv0, x1s);           // (z0', x1')
            ull c2 = pack2(y1s, sz1 * inv1);           // (y1', z1')

            ull* __restrict__ rp = sOut + i * 768 + 3 * g;
            rp[0] = c0;
            rp[1] = c1;
            rp[2] = c2;
        }
        __syncthreads();

        // Drain this half (12,288 B) with one TMA bulk store.
        if (t == 0) {
            asm volatile("fence.proxy.async.shared::cta;" ::: "memory");
            const char* gp =
                out + (size_t)(b * OUTN + u0 + 2 * hp) * (OUTN * 12);
            uint32_t sa = smem_u32(sOut + hp * 1536);
            asm volatile(
                "cp.async.bulk.global.shared::cta.bulk_group [%0], [%1], %2;"
                :: "l"(gp), "r"(sa), "r"(12288u) : "memory");
            asm volatile("cp.async.bulk.commit_group;" ::: "memory");
        }
    }

    // Wait for both drains (first is long done; only second is exposed).
    if (t == 0)
        asm volatile("cp.async.bulk.wait_group 0;" ::: "memory");
}

extern "C" void kernel_launch(void* const* d_in, const int* in_sizes, int n_in,
                              void* d_out, int out_size)
{
    const float4* ctrl   = (const float4*)d_in[0];
    const int*    uspan  = (const int*)   d_in[1];
    const int2*   vspan2 = (const int2*)  d_in[2];
    const float4* Nu4    = (const float4*)d_in[3];
    const float4* Nv4    = (const float4*)d_in[4];
    char*         out    = (char*)        d_out;

    dim3 grid(OUTN / 4, BATCH);               // 128 x 16 = 2048 blocks
    surf_fused<<<grid, 256>>>(ctrl, uspan, vspan2, Nu4, Nv4, out);
}

// round 17
// speedup vs baseline: 1.0272x; 1.0272x over previous
#include <cuda_runtime.h>
#include <cstdint>

// ctrl_pts: (16,64,64,4) f32 | uspan/vspan: (512,) i32 | Nu/Nv: (512,4) f32
// out: (16,512,512,3) f32
#define BATCH   16
#define MCTRL   64
#define NCTRL   64
#define OUTN    512
#define PDEG    3

typedef unsigned long long ull;

__device__ __forceinline__ ull pack2(float a, float b) {
    ull r; asm("mov.b64 %0, {%1,%2};" : "=l"(r) : "f"(a), "f"(b)); return r;
}
__device__ __forceinline__ void unpack2(ull v, float& a, float& b) {
    asm("mov.b64 {%0,%1}, %2;" : "=f"(a), "=f"(b) : "l"(v));
}
__device__ __forceinline__ ull mul2(ull a, ull b) {
    ull d; asm("mul.rn.f32x2 %0, %1, %2;" : "=l"(d) : "l"(a), "l"(b)); return d;
}
__device__ __forceinline__ ull fma2(ull a, ull b, ull c) {
    ull d; asm("fma.rn.f32x2 %0, %1, %2, %3;" : "=l"(d) : "l"(a), "l"(b), "l"(c)); return d;
}
__device__ __forceinline__ float rcp_approx(float x) {
    float r; asm("rcp.approx.f32 %0, %1;" : "=f"(r) : "f"(x)); return r;
}
__device__ __forceinline__ uint32_t smem_u32(const void* p) {
    uint32_t a;
    asm("{ .reg .u64 t; cvta.to.shared.u64 t, %1; cvt.u32.u64 %0, t; }"
        : "=r"(a) : "l"(p));
    return a;
}

// ---------------------------------------------------------------------------
// Fused kernel. Block = (b, 4 u-rows), 256 threads, 5 blocks/SM.
// Phase 1: A[4][64] into smem — one entry per thread.
// Phase 2: thread g owns v-pair (2g, 2g+1); 9 packed weights.
// Drain:   ASYMMETRIC pipelined TMA bulk stores — rows 0-2 (18KB) issued
//          while row 3 computes; final drain is only 6KB, halving the
//          exposed per-block tail vs the 12KB+12KB split.
// ---------------------------------------------------------------------------
__global__ __launch_bounds__(256, 5)
void surf_fused(const float4* __restrict__ ctrl,
                const int*    __restrict__ uspan,
                const int2*   __restrict__ vspan2,
                const float4* __restrict__ Nu4,
                const float4* __restrict__ Nv4,
                char*         __restrict__ out)
{
    __shared__ float4 sA[4 * NCTRL];                     // 4 KB
    __shared__ __align__(16) ull sOut[4 * 768];          // 24 KB (18 KB + 6 KB)

    int t  = threadIdx.x;                     // 0..255
    int b  = blockIdx.y;
    int u0 = blockIdx.x * 4;

    // ---- phase-2 weight setup (hoisted: overlaps phase-1 LDGs) ----
    int g = t;
    int2 vs  = __ldg(vspan2 + g);
    int  iv0 = vs.x - PDEG;
    bool sh  = vs.y != vs.x;

    ull wp0[4], wp1[5];
    {
        float4 nv0 = __ldg(Nv4 + 2 * g);
        float4 nv1 = __ldg(Nv4 + 2 * g + 1);
        wp0[0] = pack2(nv0.x, nv0.x);
        wp0[1] = pack2(nv0.y, nv0.y);
        wp0[2] = pack2(nv0.z, nv0.z);
        wp0[3] = pack2(nv0.w, nv0.w);
        float w0 = sh ? 0.0f : nv1.x;
        float w1 = sh ? nv1.x : nv1.y;
        float w2 = sh ? nv1.y : nv1.z;
        float w3 = sh ? nv1.z : nv1.w;
        float w4 = sh ? nv1.w : 0.0f;
        wp1[0] = pack2(w0, w0);
        wp1[1] = pack2(w1, w1);
        wp1[2] = pack2(w2, w2);
        wp1[3] = pack2(w3, w3);
        wp1[4] = pack2(w4, w4);
    }

    // ---------------- Phase 1: one A entry per thread ----------------
    {
        int n  = t & (NCTRL - 1);
        int ul = t >> 6;                      // 0..3
        int u  = u0 + ul;
        int iu0 = __ldg(uspan + u) - PDEG;
        const float4* __restrict__ base =
            ctrl + ((b * MCTRL + iu0) * NCTRL + n);
        float4 c0 = __ldg(base + 0 * NCTRL);
        float4 c1 = __ldg(base + 1 * NCTRL);
        float4 c2 = __ldg(base + 2 * NCTRL);
        float4 c3 = __ldg(base + 3 * NCTRL);
        float4 nu = __ldg(Nu4 + u);

        float4 acc;
        acc.x = nu.x*c0.x + nu.y*c1.x + nu.z*c2.x + nu.w*c3.x;
        acc.y = nu.x*c0.y + nu.y*c1.y + nu.z*c2.y + nu.w*c3.y;
        acc.z = nu.x*c0.z + nu.y*c1.z + nu.z*c2.z + nu.w*c3.z;
        acc.w = nu.x*c0.w + nu.y*c1.w + nu.z*c2.w + nu.w*c3.w;

        sA[ul * NCTRL + n] = acc;
    }
    __syncthreads();

    // ---------------- Phase 2: rows 0-2, then row 3 ----------------
#pragma unroll
    for (int seg = 0; seg < 2; seg++) {
        int rbeg = (seg == 0) ? 0 : 3;
        int rend = (seg == 0) ? 3 : 4;

#pragma unroll
        for (int i0 = rbeg; i0 < rend; i0++) {
            int i = i0;
            const ulonglong2* __restrict__ Ab =
                (const ulonglong2*)(sA + i * NCTRL + iv0);
            ulonglong2 A0 = Ab[0];
            ulonglong2 A1 = Ab[1];
            ulonglong2 A2 = Ab[2];
            ulonglong2 A3 = Ab[3];
            ulonglong2 A4 = Ab[4];

            // v0: 4 taps (window never shifted for first v of the pair)
            ull xy0 = mul2(wp0[0], A0.x);
            ull zw0 = mul2(wp0[0], A0.y);
            xy0 = fma2(wp0[1], A1.x, xy0);  zw0 = fma2(wp0[1], A1.y, zw0);
            xy0 = fma2(wp0[2], A2.x, xy0);  zw0 = fma2(wp0[2], A2.y, zw0);
            xy0 = fma2(wp0[3], A3.x, xy0);  zw0 = fma2(wp0[3], A3.y, zw0);

            // v1: 5 taps
            ull xy1 = mul2(wp1[0], A0.x);
            ull zw1 = mul2(wp1[0], A0.y);
            xy1 = fma2(wp1[1], A1.x, xy1);  zw1 = fma2(wp1[1], A1.y, zw1);
            xy1 = fma2(wp1[2], A2.x, xy1);  zw1 = fma2(wp1[2], A2.y, zw1);
            xy1 = fma2(wp1[3], A3.x, xy1);  zw1 = fma2(wp1[3], A3.y, zw1);
            xy1 = fma2(wp1[4], A4.x, xy1);  zw1 = fma2(wp1[4], A4.y, zw1);

            // Packed epilogue -> 24B per thread, gmem-layout order.
            float sz0, sw0, sz1, sw1;
            unpack2(zw0, sz0, sw0);
            unpack2(zw1, sz1, sw1);
            float inv0 = rcp_approx(sw0);
            float inv1 = rcp_approx(sw1);

            ull c0 = mul2(xy0, pack2(inv0, inv0));     // (x0', y0')
            ull xy1s = mul2(xy1, pack2(inv1, inv1));
            float x1s, y1s;
            unpack2(xy1s, x1s, y1s);
            ull c1 = pack2(sz0 * inv0, x1s);           // (z0', x1')
            ull c2 = pack2(y1s, sz1 * inv1);           // (y1', z1')

            ull* __restrict__ rp = sOut + i * 768 + 3 * g;
            rp[0] = c0;
            rp[1] = c1;
            rp[2] = c2;
        }
        __syncthreads();

        // Drain this segment with one TMA bulk store.
        if (t == 0) {
            asm volatile("fence.proxy.async.shared::cta;" ::: "memory");
            int rowoff   = (seg == 0) ? 0 : 3;
            uint32_t len = (seg == 0) ? 18432u : 6144u;
            const char* gp =
                out + (size_t)(b * OUTN + u0 + rowoff) * (OUTN * 12);
            uint32_t sa = smem_u32(sOut + rowoff * 768);
            asm volatile(
                "cp.async.bulk.global.shared::cta.bulk_group [%0], [%1], %2;"
                :: "l"(gp), "r"(sa), "r"(len) : "memory");
            asm volatile("cp.async.bulk.commit_group;" ::: "memory");
        }
    }

    // Wait for both drains (first is long done; only the 6KB one exposed).
    if (t == 0)
        asm volatile("cp.async.bulk.wait_group 0;" ::: "memory");
}

extern "C" void kernel_launch(void* const* d_in, const int* in_sizes, int n_in,
                              void* d_out, int out_size)
{
    const float4* ctrl   = (const float4*)d_in[0];
    const int*    uspan  = (const int*)   d_in[1];
    const int2*   vspan2 = (const int2*)  d_in[2];
    const float4* Nu4    = (const float4*)d_in[3];
    const float4* Nv4    = (const float4*)d_in[4];
    char*         out    = (char*)        d_out;

    dim3 grid(OUTN / 4, BATCH);               // 128 x 16 = 2048 blocks
    surf_fused<<<grid, 256>>>(ctrl, uspan, vspan2, Nu4, Nv4, out);
}